// round 15
// baseline (speedup 1.0000x reference)
#include <cuda_runtime.h>
#include <cuda_bf16.h>
#include <math.h>

#define BB 4
#define TT 2048
#define DD 1024
#define HH 16
#define DH 64
#define MTOT (BB*TT)            // 8192
#define OUT0 (BB*TT*DD)         // 8388608 floats: "out" part of d_out

// Scratch (static device arrays; runtime alloc forbidden)
__device__ float g_q[BB*HH*TT*DH];
__device__ float g_k[BB*HH*TT*DH];
__device__ float g_v[BB*HH*TT*DH];
__device__ float g_ctx[BB*TT*DD];

// ---------------------------------------------------------------------------
// SGEMM: C[M,N] = A[M,K] @ B[K,N] + bias     (R8: register-prefetch, 2-barrier)
// MODE 0: A = g_ctx, plain row-major epilogue into C
// MODE 1: A = Ain (x), epilogue scatters into g_q/g_k/g_v in [b][h][t][dh]
// ---------------------------------------------------------------------------
template<int MODE>
__global__ __launch_bounds__(256)
void sgemm_k(const float* __restrict__ Ain, const float* __restrict__ Bw,
             const float* __restrict__ bias, float* __restrict__ C,
             int M, int N, int K) {
    __shared__ float As[16][132];   // transposed A tile: As[kk][m]
    __shared__ float Bs[16][132];   // natural B tile:    Bs[kk][n]

    const float* A = (MODE == 0) ? g_ctx : Ain;
    const int tid = threadIdx.x;
    const int tx = tid & 15, ty = tid >> 4;
    const int m0 = blockIdx.y * 128, n0 = blockIdx.x * 128;

    const int arow0 = (tid + 0) >> 2,        ac0 = ((tid + 0) & 3) * 4;
    const int arow1 = (tid + 256) >> 2,      ac1 = ((tid + 256) & 3) * 4;
    const int brow0 = (tid + 0) >> 5,        bc0 = ((tid + 0) & 31) * 4;
    const int brow1 = (tid + 256) >> 5,      bc1 = ((tid + 256) & 31) * 4;

    float acc[8][8];
    #pragma unroll
    for (int i = 0; i < 8; i++)
        #pragma unroll
        for (int j = 0; j < 8; j++) acc[i][j] = 0.f;

    float4 pa0 = *reinterpret_cast<const float4*>(&A[(size_t)(m0 + arow0) * K + ac0]);
    float4 pa1 = *reinterpret_cast<const float4*>(&A[(size_t)(m0 + arow1) * K + ac1]);
    float4 pb0 = *reinterpret_cast<const float4*>(&Bw[(size_t)brow0 * N + n0 + bc0]);
    float4 pb1 = *reinterpret_cast<const float4*>(&Bw[(size_t)brow1 * N + n0 + bc1]);

    for (int k0 = 0; k0 < K; k0 += 16) {
        As[ac0 + 0][arow0] = pa0.x; As[ac0 + 1][arow0] = pa0.y;
        As[ac0 + 2][arow0] = pa0.z; As[ac0 + 3][arow0] = pa0.w;
        As[ac1 + 0][arow1] = pa1.x; As[ac1 + 1][arow1] = pa1.y;
        As[ac1 + 2][arow1] = pa1.z; As[ac1 + 3][arow1] = pa1.w;
        *reinterpret_cast<float4*>(&Bs[brow0][bc0]) = pb0;
        *reinterpret_cast<float4*>(&Bs[brow1][bc1]) = pb1;
        __syncthreads();

        if (k0 + 16 < K) {
            pa0 = *reinterpret_cast<const float4*>(&A[(size_t)(m0 + arow0) * K + k0 + 16 + ac0]);
            pa1 = *reinterpret_cast<const float4*>(&A[(size_t)(m0 + arow1) * K + k0 + 16 + ac1]);
            pb0 = *reinterpret_cast<const float4*>(&Bw[(size_t)(k0 + 16 + brow0) * N + n0 + bc0]);
            pb1 = *reinterpret_cast<const float4*>(&Bw[(size_t)(k0 + 16 + brow1) * N + n0 + bc1]);
        }

        #pragma unroll
        for (int kk = 0; kk < 16; kk++) {
            float a[8], b[8];
            *reinterpret_cast<float4*>(&a[0]) = *reinterpret_cast<float4*>(&As[kk][ty * 8]);
            *reinterpret_cast<float4*>(&a[4]) = *reinterpret_cast<float4*>(&As[kk][ty * 8 + 4]);
            *reinterpret_cast<float4*>(&b[0]) = *reinterpret_cast<float4*>(&Bs[kk][tx * 8]);
            *reinterpret_cast<float4*>(&b[4]) = *reinterpret_cast<float4*>(&Bs[kk][tx * 8 + 4]);
            #pragma unroll
            for (int i = 0; i < 8; i++)
                #pragma unroll
                for (int j = 0; j < 8; j++) acc[i][j] += a[i] * b[j];
        }
        __syncthreads();
    }

    if (MODE == 0) {
        #pragma unroll
        for (int i = 0; i < 8; i++) {
            int row = m0 + ty * 8 + i;
            #pragma unroll
            for (int j0 = 0; j0 < 8; j0 += 4) {
                int col = n0 + tx * 8 + j0;
                float4 v;
                v.x = acc[i][j0 + 0] + bias[col + 0];
                v.y = acc[i][j0 + 1] + bias[col + 1];
                v.z = acc[i][j0 + 2] + bias[col + 2];
                v.w = acc[i][j0 + 3] + bias[col + 3];
                *reinterpret_cast<float4*>(&C[(size_t)row * N + col]) = v;
            }
        }
    } else {
        #pragma unroll
        for (int i = 0; i < 8; i++) {
            int row = m0 + ty * 8 + i;
            int bb = row >> 11, t = row & 2047;
            #pragma unroll
            for (int j = 0; j < 8; j++) {
                int n = n0 + tx * 8 + j;
                int which = n >> 10;
                int rem = n & 1023;
                int h = rem >> 6, dh = rem & 63;
                float v = acc[i][j] + bias[n];
                float* dst = (which == 0) ? g_q : (which == 1) ? g_k : g_v;
                dst[(((size_t)(bb * HH + h)) * TT + t) * DH + dh] = v;
            }
        }
    }
}

// ---------------------------------------------------------------------------
// Attention: one block per (b, h, 16-query tile). Full 16x2048 score strip in
// smem -> exact softmax, weights written once, context from smem scores.
// P1: 4 rows x 2 keys per thread; q hoisted as float4 per 4 kk.
// P2: all three softmax passes + weight stores vectorized to float4.
// P3: 4 rows x 1 col per thread; weights hoisted as float4 per 4 j.
// ---------------------------------------------------------------------------
#define SM_QS   0                       // [16][64]
#define SM_KT   1024                    // [64][128] swizzled float4 columns
#define SM_VB   (1024 + 8192)           // [128][68]
#define SM_SS   (1024 + 8192 + 8704)    // [16][2048]
#define ATTN_SMEM_FLOATS (1024 + 8192 + 8704 + 32768)
#define ATTN_SMEM_BYTES  (ATTN_SMEM_FLOATS * 4)   // 202752

__global__ __launch_bounds__(256)
void attn_kernel(float* __restrict__ wout) {
    extern __shared__ float sm[];
    float* qs = sm + SM_QS;
    float* kT = sm + SM_KT;
    float* vb = sm + SM_VB;
    float* sS = sm + SM_SS;

    const int tid = threadIdx.x;
    const int qt = blockIdx.x, h = blockIdx.y, b = blockIdx.z;
    const int q0 = qt * 16;
    const size_t hb = ((size_t)(b * HH + h)) * TT;

    // ---- load Q tile, pre-scaled by 1/sqrt(64) = 0.125 ----
    {
        int r = tid >> 4, c = (tid & 15) * 4;
        float4 v = *reinterpret_cast<const float4*>(&g_q[(hb + q0 + r) * DH + c]);
        qs[r * 64 + c + 0] = v.x * 0.125f;
        qs[r * 64 + c + 1] = v.y * 0.125f;
        qs[r * 64 + c + 2] = v.z * 0.125f;
        qs[r * 64 + c + 3] = v.w * 0.125f;
    }

    const int nch = (q0 + 16 + 127) >> 7;   // 128-key chunks covering causal span
    const int Lc = nch << 7;

    // ---- phase 1: scores -> sS (masked with -1e30) ----
    {
        const int rg4 = tid >> 6;    // 4 row groups of 4 rows (uniform per warp)
        const int cg2 = tid & 63;    // 64 col groups of 2 keys
        const int kq = cg2 >> 1, half2 = (cg2 & 1) * 2;
        for (int c = 0; c < nch; c++) {
            const int kb = c << 7;
            __syncthreads();   // kT reuse safe / qs ready on first iter
            #pragma unroll
            for (int i = 0; i < 2; i++) {
                int gid = tid + i * 256;
                int kq2 = gid >> 4, c4 = gid & 15;
                float vr[4][4];
                #pragma unroll
                for (int jj = 0; jj < 4; jj++) {
                    float4 t4 = *reinterpret_cast<const float4*>(
                        &g_k[(hb + kb + kq2 * 4 + jj) * DH + c4 * 4]);
                    vr[jj][0] = t4.x; vr[jj][1] = t4.y;
                    vr[jj][2] = t4.z; vr[jj][3] = t4.w;
                }
                #pragma unroll
                for (int dd = 0; dd < 4; dd++) {
                    int row = c4 * 4 + dd;
                    int p = kq2 ^ (row & 31);
                    *reinterpret_cast<float4*>(&kT[row * 128 + p * 4]) =
                        make_float4(vr[0][dd], vr[1][dd], vr[2][dd], vr[3][dd]);
                }
            }
            __syncthreads();
            float acc[4][2];
            #pragma unroll
            for (int i = 0; i < 4; i++) { acc[i][0] = 0.f; acc[i][1] = 0.f; }
            #pragma unroll
            for (int kk = 0; kk < 64; kk += 4) {
                float4 qv4[4];
                #pragma unroll
                for (int i = 0; i < 4; i++)
                    qv4[i] = *reinterpret_cast<const float4*>(
                        &qs[(rg4 * 4 + i) * 64 + kk]);
                #pragma unroll
                for (int u = 0; u < 4; u++) {
                    const int k2 = kk + u;
                    float2 kv = *reinterpret_cast<const float2*>(
                        &kT[k2 * 128 + ((kq ^ (k2 & 31)) << 2) + half2]);
                    #pragma unroll
                    for (int i = 0; i < 4; i++) {
                        float qv = (u == 0) ? qv4[i].x : (u == 1) ? qv4[i].y
                                 : (u == 2) ? qv4[i].z : qv4[i].w;
                        acc[i][0] += qv * kv.x;
                        acc[i][1] += qv * kv.y;
                    }
                }
            }
            #pragma unroll
            for (int i = 0; i < 4; i++) {
                int row = rg4 * 4 + i;
                int qg = q0 + row;
                int kbase = kb + cg2 * 2;
                float2 o;
                o.x = (kbase + 0 <= qg) ? acc[i][0] : -1e30f;
                o.y = (kbase + 1 <= qg) ? acc[i][1] : -1e30f;
                *reinterpret_cast<float2*>(&sS[row * 2048 + kbase]) = o;
            }
        }
    }
    __syncthreads();

    // ---- phase 2: exact softmax (float4 passes), write weights ----
    {
        const int warp = tid >> 5, lane = tid & 31;
        for (int i = warp; i < 16; i += 8) {
            float* row = &sS[i * 2048];
            float mx = -1e30f;
            for (int j = lane * 4; j < Lc; j += 128) {
                float4 v = *reinterpret_cast<const float4*>(&row[j]);
                mx = fmaxf(mx, fmaxf(fmaxf(v.x, v.y), fmaxf(v.z, v.w)));
            }
            #pragma unroll
            for (int o = 16; o; o >>= 1) mx = fmaxf(mx, __shfl_xor_sync(0xffffffffu, mx, o));
            float s = 0.f;
            for (int j = lane * 4; j < Lc; j += 128) {
                float4 v = *reinterpret_cast<const float4*>(&row[j]);
                v.x = __expf(v.x - mx);
                v.y = __expf(v.y - mx);
                v.z = __expf(v.z - mx);
                v.w = __expf(v.w - mx);
                s += (v.x + v.y) + (v.z + v.w);
                *reinterpret_cast<float4*>(&row[j]) = v;
            }
            #pragma unroll
            for (int o = 16; o; o >>= 1) s += __shfl_xor_sync(0xffffffffu, s, o);
            float inv = 1.0f / s;
            float* wr = &wout[(hb + q0 + i) * TT];
            for (int j = lane * 4; j < Lc; j += 128) {
                float4 v = *reinterpret_cast<const float4*>(&row[j]);
                v.x *= inv; v.y *= inv; v.z *= inv; v.w *= inv;
                *reinterpret_cast<float4*>(&row[j]) = v;
                *reinterpret_cast<float4*>(&wr[j]) = v;
            }
            const float4 z4 = make_float4(0.f, 0.f, 0.f, 0.f);
            for (int j = Lc + lane * 4; j < TT; j += 128)
                *reinterpret_cast<float4*>(&wr[j]) = z4;
        }
    }
    __syncthreads();

    // ---- phase 3: context = W @ V  (4 rows x 1 col; w hoisted as float4) ----
    {
        const int r2 = tid >> 6;    // 4 row groups of 4 rows (uniform per warp)
        const int c3 = tid & 63;    // 64 columns
        float a[4] = {0.f, 0.f, 0.f, 0.f};
        for (int c = 0; c < nch; c++) {
            const int kb = c << 7;
            __syncthreads();   // vb reuse safe
            #pragma unroll
            for (int i = 0; i < 8; i++) {
                int idx = tid + i * 256;
                int key = idx >> 4, c4 = (idx & 15) * 4;
                *reinterpret_cast<float4*>(&vb[key * 68 + c4]) =
                    *reinterpret_cast<const float4*>(
                        &g_v[(hb + kb + key) * DH + c4]);
            }
            __syncthreads();
            #pragma unroll 2
            for (int j = 0; j < 128; j += 4) {
                float4 w4[4];
                #pragma unroll
                for (int i = 0; i < 4; i++)
                    w4[i] = *reinterpret_cast<const float4*>(
                        &sS[(r2 * 4 + i) * 2048 + kb + j]);
                #pragma unroll
                for (int u = 0; u < 4; u++) {
                    float vv = vb[(j + u) * 68 + c3];
                    #pragma unroll
                    for (int i = 0; i < 4; i++) {
                        float wv = (u == 0) ? w4[i].x : (u == 1) ? w4[i].y
                                 : (u == 2) ? w4[i].z : w4[i].w;
                        a[i] += wv * vv;
                    }
                }
            }
        }
        #pragma unroll
        for (int i = 0; i < 4; i++)
            g_ctx[((size_t)(b * TT + q0 + r2 * 4 + i)) * DD + h * 64 + c3] = a[i];
    }
}

// ---------------------------------------------------------------------------
extern "C" void kernel_launch(void* const* d_in, const int* in_sizes, int n_in,
                              void* d_out, int out_size) {
    const float* x     = (const float*)d_in[0];
    const float* w_qkv = (const float*)d_in[1];
    const float* b_qkv = (const float*)d_in[2];
    const float* w_out = (const float*)d_in[3];
    const float* b_out = (const float*)d_in[4];
    float* out     = (float*)d_out;          // (B,T,D)
    float* weights = out + OUT0;             // (B,H,T,T)

    (void)in_sizes; (void)n_in; (void)out_size;

    cudaFuncSetAttribute(attn_kernel,
                         cudaFuncAttributeMaxDynamicSharedMemorySize,
                         ATTN_SMEM_BYTES);

    // 1) QKV projection, scattered into per-head Q/K/V layout
    sgemm_k<1><<<dim3(3 * DD / 128, MTOT / 128), 256>>>(
        x, w_qkv, b_qkv, nullptr, MTOT, 3 * DD, DD);

    // 2) causal attention: weights out + context
    attn_kernel<<<dim3(TT / 16, HH, BB), 256, ATTN_SMEM_BYTES>>>(weights);

    // 3) output projection
    sgemm_k<0><<<dim3(DD / 128, MTOT / 128), 256>>>(
        nullptr, w_out, b_out, out, MTOT, DD, DD);
}